// round 1
// baseline (speedup 1.0000x reference)
#include <cuda_runtime.h>
#include <cstdint>

// 1x1 conv as GEMM: out[b,o,hw] = sum_i w[i,o] * x[b,i,hw]
// B=32, CIN=COUT=128, HW=128*128=16384.
// CTA: 128 outputs (all of COUT) x 128 spatial positions. 256 threads,
// each computes an 8m x 8n micro-tile using packed fma.rn.f32x2 (FFMA2).

#define CIN   128
#define COUT  128
#define HW    16384
#define NTILE 128
#define KC    16
#define NCHUNK (CIN / KC)   // 8

#define SMEM_BYTES (CIN*COUT*4 + 2*KC*NTILE*4)   // 65536 + 16384 = 81920

__global__ __launch_bounds__(256, 2)
void conv1x1_f32x2_kernel(const float* __restrict__ x,
                          const float* __restrict__ w,
                          float* __restrict__ out)
{
    extern __shared__ float smem[];
    float* Ws = smem;                    // [128 k][128 m], row-major (same as gmem weight)
    float* Xs = smem + CIN * COUT;       // [2][KC][NTILE]

    const int tid = threadIdx.x;
    const int tx  = tid & 15;            // n-group: covers n = tx*8 .. tx*8+7
    const int ty  = tid >> 4;            // m-group: covers m = ty*8 .. ty*8+7

    const int n0  = blockIdx.x * NTILE;  // global spatial index
    const int b   = n0 / HW;
    const int hw0 = n0 - b * HW;         // NTILE-aligned, never crosses batch (HW % NTILE == 0)

    const float* xbase = x + (size_t)b * CIN * HW + hw0;

    // ---- load entire weight [CIN][COUT] into SMEM (coalesced float4) ----
    {
        const float4* wg  = (const float4*)w;
        float4*       wsv = (float4*)Ws;
        #pragma unroll
        for (int i = 0; i < 16; i++)
            wsv[tid + i * 256] = wg[tid + i * 256];
    }

    // ---- prefetch x chunk 0 into SMEM buffer 0 ----
    const int lkc = tid >> 4;            // k-row within chunk (0..15)
    const int lj  = (tid & 15) * 2;      // float4 column (0..30, step 2)
    float4 r0, r1;
    {
        const float4* g = (const float4*)(xbase + lkc * HW);
        r0 = g[lj];
        r1 = g[lj + 1];
    }
    {
        float4* s = (float4*)(Xs + lkc * NTILE);
        s[lj]     = r0;
        s[lj + 1] = r1;
    }
    __syncthreads();

    // packed f32x2 accumulators: acc[m][n2] holds outputs (m, 2*n2) and (m, 2*n2+1)
    unsigned long long acc[8][4];
    #pragma unroll
    for (int i = 0; i < 8; i++)
        #pragma unroll
        for (int j = 0; j < 4; j++)
            acc[i][j] = 0ULL;

    const float4* Ws4 = (const float4*)Ws;

    #pragma unroll 1
    for (int c = 0; c < NCHUNK; c++) {
        const float4* Xs4 = (const float4*)(Xs + (c & 1) * (KC * NTILE));

        // prefetch next chunk into registers (hidden under compute)
        if (c + 1 < NCHUNK) {
            const float4* g = (const float4*)(xbase + ((c + 1) * KC + lkc) * HW);
            r0 = g[lj];
            r1 = g[lj + 1];
        }

        #pragma unroll
        for (int k = 0; k < KC; k++) {
            const int krow = c * KC + k;
            float4 a0 = Ws4[krow * 32 + ty * 2];      // w[k][ty*8 .. +3]
            float4 a1 = Ws4[krow * 32 + ty * 2 + 1];  // w[k][ty*8+4 .. +7]
            float4 b0 = Xs4[k * 32 + tx * 2];         // x[k][tx*8 .. +3]
            float4 b1 = Xs4[k * 32 + tx * 2 + 1];     // x[k][tx*8+4 .. +7]

            unsigned long long bp[4];
            asm("mov.b64 %0, {%1, %2};" : "=l"(bp[0]) : "f"(b0.x), "f"(b0.y));
            asm("mov.b64 %0, {%1, %2};" : "=l"(bp[1]) : "f"(b0.z), "f"(b0.w));
            asm("mov.b64 %0, {%1, %2};" : "=l"(bp[2]) : "f"(b1.x), "f"(b1.y));
            asm("mov.b64 %0, {%1, %2};" : "=l"(bp[3]) : "f"(b1.z), "f"(b1.w));

            float am[8] = {a0.x, a0.y, a0.z, a0.w, a1.x, a1.y, a1.z, a1.w};

            #pragma unroll
            for (int m = 0; m < 8; m++) {
                unsigned long long ap;
                asm("mov.b64 %0, {%1, %1};" : "=l"(ap) : "f"(am[m]));
                #pragma unroll
                for (int j = 0; j < 4; j++) {
                    asm("fma.rn.f32x2 %0, %1, %2, %0;"
                        : "+l"(acc[m][j]) : "l"(ap), "l"(bp[j]));
                }
            }
        }

        if (c + 1 < NCHUNK) {
            __syncthreads();   // everyone done reading buffer (c+1)&1 (used in chunk c-1)
            float4* s = (float4*)(Xs + ((c + 1) & 1) * (KC * NTILE) + lkc * NTILE);
            s[lj]     = r0;
            s[lj + 1] = r1;
            __syncthreads();   // stores visible before next chunk's compute
        }
    }

    // ---- epilogue: unpack and store (coalesced float4) ----
    float* obase = out + (size_t)b * COUT * HW + hw0 + tx * 8;
    #pragma unroll
    for (int m = 0; m < 8; m++) {
        const int o = ty * 8 + m;
        float v0, v1, v2, v3, v4, v5, v6, v7;
        asm("mov.b64 {%0, %1}, %2;" : "=f"(v0), "=f"(v1) : "l"(acc[m][0]));
        asm("mov.b64 {%0, %1}, %2;" : "=f"(v2), "=f"(v3) : "l"(acc[m][1]));
        asm("mov.b64 {%0, %1}, %2;" : "=f"(v4), "=f"(v5) : "l"(acc[m][2]));
        asm("mov.b64 {%0, %1}, %2;" : "=f"(v6), "=f"(v7) : "l"(acc[m][3]));
        float4* po = (float4*)(obase + (size_t)o * HW);
        po[0] = make_float4(v0, v1, v2, v3);
        po[1] = make_float4(v4, v5, v6, v7);
    }
}

extern "C" void kernel_launch(void* const* d_in, const int* in_sizes, int n_in,
                              void* d_out, int out_size)
{
    const float* x   = (const float*)d_in[0];   // (32, 128, 128, 128) fp32
    const float* w   = (const float*)d_in[1];   // (128, 128) fp32
    float*       out = (float*)d_out;           // (32, 128, 128, 128) fp32

    cudaFuncSetAttribute(conv1x1_f32x2_kernel,
                         cudaFuncAttributeMaxDynamicSharedMemorySize, SMEM_BYTES);

    const int grid = (32 * HW) / NTILE;  // 4096 CTAs
    conv1x1_f32x2_kernel<<<grid, 256, SMEM_BYTES>>>(x, w, out);
}

// round 3
// speedup vs baseline: 2.9037x; 2.9037x over previous
#include <cuda_runtime.h>
#include <cstdint>

// 1x1 conv as GEMM via mma.sync tf32 (baseline PTX, works on sm_103 non-'a').
// D[m=hw][n=cout] = sum_k x[k][m] * w[k][n]
// CTA tile 128m x 128n, K=128. 8 warps of 32m x 64n. Persistent CTAs.
// Weight pre-packed into per-lane B-fragment layout (conflict-free LDS.64).
// x staged via cp.async into XOR-swizzled [k][m] smem (conflict-free A LDS).

#define CIN    128
#define COUT   128
#define HW     16384
#define NTILES 4096
#define GRID   304
#define THREADS 256

#define WF_BYTES   65536              // 16 kstep x 16 ntile x 32 lane x 8B
#define XBUF_BYTES (32 * 128 * 4)     // one 32k x 128m chunk
#define SMEM_BYTES (WF_BYTES + 2 * XBUF_BYTES)   // 98304

__device__ __forceinline__ uint32_t smem_u32(const void* p) {
    uint32_t a;
    asm("{ .reg .u64 t; cvta.to.shared.u64 t, %1; cvt.u32.u64 %0, t; }" : "=r"(a) : "l"(p));
    return a;
}
__device__ __forceinline__ uint32_t f2tf32(float v) {
    uint32_t u;
    asm("cvt.rna.tf32.f32 %0, %1;" : "=r"(u) : "f"(v));
    return u;
}
__device__ __forceinline__ void cp16(uint32_t dst, const float* src) {
    asm volatile("cp.async.cg.shared.global [%0], [%1], 16;" :: "r"(dst), "l"(src) : "memory");
}
__device__ __forceinline__ uint32_t lds32(uint32_t a) {
    uint32_t v;
    asm volatile("ld.shared.b32 %0, [%1];" : "=r"(v) : "r"(a));
    return v;
}

#define MMA(d, a0, a1, a2, a3, b0, b1)                                         \
    asm volatile("mma.sync.aligned.m16n8k8.row.col.f32.tf32.tf32.f32 "         \
                 "{%0,%1,%2,%3}, {%4,%5,%6,%7}, {%8,%9}, {%0,%1,%2,%3};"       \
                 : "+f"(d[0]), "+f"(d[1]), "+f"(d[2]), "+f"(d[3])              \
                 : "r"(a0), "r"(a1), "r"(a2), "r"(a3), "r"(b0), "r"(b1))

__global__ __launch_bounds__(THREADS, 2)
void conv1x1_mma_tf32(const float* __restrict__ x,
                      const float* __restrict__ w,
                      float* __restrict__ out)
{
    extern __shared__ char smem[];
    const uint32_t sb = smem_u32(smem);
    const uint32_t wf = sb;               // packed B fragments
    const uint32_t xs = sb + WF_BYTES;    // x chunk buffers (x2)

    const int tid  = threadIdx.x;
    const int lane = tid & 31;
    const int wid  = tid >> 5;
    const int wm   = (wid >> 1) * 32;     // warp m offset (0,32,64,96)
    const int wnt  = (wid & 1) * 8;       // warp ntile offset (0 or 8)

    const int g = lane >> 2;              // groupID
    const int c = lane & 3;               // threadID_in_group

    // ---- prologue: start DMA of first tile's chunk 0 (overlaps weight packing) ----
    int t0 = blockIdx.x;
    {
        const int b   = t0 >> 7;
        const int hw0 = (t0 & 127) << 7;
        const float* xb = x + (size_t)b * CIN * HW + hw0;
        const int krow = tid >> 5;
        const int m4   = (tid & 31) * 4;
        #pragma unroll
        for (int p = 0; p < 4; p++) {
            const int k = p * 8 + krow;                         // 0..31
            const uint32_t pm = (uint32_t)m4 ^ (uint32_t)((k & 3) << 3);
            cp16(xs + (uint32_t)(k * 128 + pm) * 4, xb + (size_t)k * HW + m4);
        }
        asm volatile("cp.async.commit_group;" ::: "memory");
    }

    // ---- pack weights into per-lane B fragment layout (tf32-converted) ----
    // Wf[s][t][lane] = { w[s*8 + (lane&3)][t*8 + (lane>>2)], w[s*8 + (lane&3) + 4][same n] }
    for (int idx = tid; idx < 8192; idx += THREADS) {
        const int s  = idx >> 9;
        const int r  = idx & 511;
        const int tn = r >> 5;
        const int l  = r & 31;
        const int k0 = s * 8 + (l & 3);
        const int n  = tn * 8 + (l >> 2);
        const uint32_t b0 = f2tf32(w[k0 * COUT + n]);
        const uint32_t b1 = f2tf32(w[(k0 + 4) * COUT + n]);
        asm volatile("st.shared.v2.b32 [%0], {%1,%2};"
                     :: "r"(wf + (uint32_t)idx * 8), "r"(b0), "r"(b1) : "memory");
    }

    int cc = 0;   // global chunk counter (parity -> buffer)

    for (int t = t0; t < NTILES; t += GRID) {
        const int b   = t >> 7;
        const int hw0 = (t & 127) << 7;
        const float* xb = x + (size_t)b * CIN * HW + hw0;

        float acc[2][8][4];
        #pragma unroll
        for (int mt = 0; mt < 2; mt++)
            #pragma unroll
            for (int nt = 0; nt < 8; nt++)
                #pragma unroll
                for (int j = 0; j < 4; j++)
                    acc[mt][nt][j] = 0.0f;

        #pragma unroll 1
        for (int ch = 0; ch < 4; ch++) {
            asm volatile("cp.async.wait_group 0;" ::: "memory");
            __syncthreads();

            // issue next chunk (this tile's ch+1, or next tile's chunk 0)
            {
                const float* nxb = nullptr;
                int nk = 0;
                if (ch < 3)                 { nxb = xb; nk = (ch + 1) * 32; }
                else if (t + GRID < NTILES) {
                    const int t2   = t + GRID;
                    nxb = x + (size_t)(t2 >> 7) * CIN * HW + ((t2 & 127) << 7);
                    nk  = 0;
                }
                if (nxb) {
                    const uint32_t dstb = xs + (uint32_t)((cc + 1) & 1) * XBUF_BYTES;
                    const int krow = tid >> 5;
                    const int m4   = (tid & 31) * 4;
                    #pragma unroll
                    for (int p = 0; p < 4; p++) {
                        const int k = p * 8 + krow;
                        const uint32_t pm = (uint32_t)m4 ^ (uint32_t)((k & 3) << 3);
                        cp16(dstb + (uint32_t)(k * 128 + pm) * 4,
                             nxb + (size_t)(nk + k) * HW + m4);
                    }
                    asm volatile("cp.async.commit_group;" ::: "memory");
                }
            }

            // compute 4 k-steps (k8 each) from buffer cc&1
            const uint32_t xbuf = xs + (uint32_t)(cc & 1) * XBUF_BYTES;
            #pragma unroll
            for (int s2 = 0; s2 < 4; s2++) {
                const int s  = ch * 4 + s2;      // global kstep 0..15
                const int kl = s2 * 8 + c;       // within-chunk k row for a0

                // A fragments (conflict-free swizzled LDS)
                uint32_t a[2][4];
                #pragma unroll
                for (int mt = 0; mt < 2; mt++) {
                    const uint32_t m0 = (uint32_t)(wm + 16 * mt + g);
                    const uint32_t p0 = m0 ^ (uint32_t)(c << 3);
                    const uint32_t ad0 = xbuf + (uint32_t)(kl * 128 + p0) * 4;
                    const uint32_t ad1 = ad0 ^ 32u;        // m + 8
                    a[mt][0] = f2tf32(__uint_as_float(lds32(ad0)));
                    a[mt][1] = f2tf32(__uint_as_float(lds32(ad1)));
                    a[mt][2] = f2tf32(__uint_as_float(lds32(ad0 + 2048u)));  // k + 4
                    a[mt][3] = f2tf32(__uint_as_float(lds32(ad1 + 2048u)));
                }

                // B fragments (pre-packed, one LDS.64 each) + MMAs
                #pragma unroll
                for (int nt = 0; nt < 8; nt++) {
                    uint32_t b0, b1;
                    const uint32_t ba = wf +
                        (uint32_t)(((s * 16 + wnt + nt) * 32 + lane)) * 8;
                    asm volatile("ld.shared.v2.b32 {%0,%1}, [%2];"
                                 : "=r"(b0), "=r"(b1) : "r"(ba));
                    MMA(acc[0][nt], a[0][0], a[0][1], a[0][2], a[0][3], b0, b1);
                    MMA(acc[1][nt], a[1][0], a[1][1], a[1][2], a[1][3], b0, b1);
                }
            }
            cc++;
        }

        // ---- epilogue: direct stores (32B-sector aligned groups) ----
        float* ob = out + (size_t)b * COUT * HW + hw0;
        #pragma unroll
        for (int mt = 0; mt < 2; mt++) {
            const int m0 = wm + 16 * mt + g;
            #pragma unroll
            for (int nt = 0; nt < 8; nt++) {
                const int n0 = (wnt + nt) * 8 + 2 * c;
                ob[(size_t)n0 * HW + m0]           = acc[mt][nt][0];
                ob[(size_t)(n0 + 1) * HW + m0]     = acc[mt][nt][1];
                ob[(size_t)n0 * HW + m0 + 8]       = acc[mt][nt][2];
                ob[(size_t)(n0 + 1) * HW + m0 + 8] = acc[mt][nt][3];
            }
        }
    }
}

extern "C" void kernel_launch(void* const* d_in, const int* in_sizes, int n_in,
                              void* d_out, int out_size)
{
    const float* x   = (const float*)d_in[0];   // (32, 128, 128, 128) fp32
    const float* w   = (const float*)d_in[1];   // (128, 128) fp32
    float*       out = (float*)d_out;

    cudaFuncSetAttribute(conv1x1_mma_tf32,
                         cudaFuncAttributeMaxDynamicSharedMemorySize, SMEM_BYTES);
    conv1x1_mma_tf32<<<GRID, THREADS, SMEM_BYTES>>>(x, w, out);
}